// round 12
// baseline (speedup 1.0000x reference)
#include <cuda_runtime.h>
#include <cuda_bf16.h>
#include <cstdint>

#define B_ROWS 16384
#define C_ROWS 4096
#define DDIM   1024

// GEMM tiling
#define TM 128            // CTA M
#define TN 128            // CTA N
#define TK 64             // K chunk (per pipeline stage)
#define NSTAGE 3
#define KCHUNKS (DDIM / TK)        // 16
#define K16S (TK / 16)             // 4 mma k-steps per chunk

#define A_STAGE_BYTES (TM * TK * 2)            // 16384
#define B_STAGE_BYTES (TN * TK * 2)            // 16384
#define STAGE_BYTES (A_STAGE_BYTES + B_STAGE_BYTES)   // 32768
#define SMEM_DYN (1024 + NSTAGE * STAGE_BYTES)        // 99328  -> 2 CTAs/SM

// ---- device scratch (allocation-free rule: __device__ globals) ----
__device__ __align__(16) __nv_bfloat16 g_feat_bf16[B_ROWS * DDIM];   // 32 MB
__device__ __align__(16) __nv_bfloat16 g_cent_bf16[C_ROWS * DDIM];   // 8 MB
__device__ float g_x2[B_ROWS];
__device__ float g_c2[C_ROWS];

// ============================ PTX helpers (baseline PTX only) ============================
__device__ __forceinline__ uint32_t smem_u32(const void* p) {
    return (uint32_t)__cvta_generic_to_shared(p);
}

#define CP_ASYNC16(smem_addr, gptr) \
    asm volatile("cp.async.cg.shared.global [%0], [%1], 16;" \
                 :: "r"((uint32_t)(smem_addr)), "l"(gptr) : "memory")

#define CP_ASYNC_COMMIT() asm volatile("cp.async.commit_group;" ::: "memory")
#define CP_ASYNC_WAIT1()  asm volatile("cp.async.wait_group 1;" ::: "memory")

#define LDSM_X4(r, addr) \
    asm volatile("ldmatrix.sync.aligned.m8n8.x4.shared.b16 {%0,%1,%2,%3}, [%4];" \
                 : "=r"((r)[0]), "=r"((r)[1]), "=r"((r)[2]), "=r"((r)[3]) \
                 : "r"((uint32_t)(addr)))

#define MMA_BF16(d, a, b0, b1) \
    asm volatile("mma.sync.aligned.m16n8k16.row.col.f32.bf16.bf16.f32 " \
                 "{%0,%1,%2,%3}, {%4,%5,%6,%7}, {%8,%9}, {%0,%1,%2,%3};" \
                 : "+f"((d)[0]), "+f"((d)[1]), "+f"((d)[2]), "+f"((d)[3]) \
                 : "r"((a)[0]), "r"((a)[1]), "r"((a)[2]), "r"((a)[3]), \
                   "r"(b0), "r"(b1))

// ============================ prep kernel ============================
// One warp per row: fp32 -> bf16 + squared row norm. 20480 warps.
__global__ void prep_kernel(const float* __restrict__ feat, const float* __restrict__ cent) {
    int gw = (blockIdx.x * blockDim.x + threadIdx.x) >> 5;
    int lane = threadIdx.x & 31;
    if (gw >= B_ROWS + C_ROWS) return;

    const float* src;
    __nv_bfloat16* dst;
    float* nrm;
    if (gw < B_ROWS) {
        src = feat + (size_t)gw * DDIM;
        dst = g_feat_bf16 + (size_t)gw * DDIM;
        nrm = g_x2 + gw;
    } else {
        int r = gw - B_ROWS;
        src = cent + (size_t)r * DDIM;
        dst = g_cent_bf16 + (size_t)r * DDIM;
        nrm = g_c2 + r;
    }

    float s = 0.0f;
    #pragma unroll
    for (int i = 0; i < DDIM / 128; i++) {
        int idx = i * 128 + lane * 4;
        float4 v = *reinterpret_cast<const float4*>(src + idx);
        s = fmaf(v.x, v.x, s); s = fmaf(v.y, v.y, s);
        s = fmaf(v.z, v.z, s); s = fmaf(v.w, v.w, s);
        __nv_bfloat162 p0 = __floats2bfloat162_rn(v.x, v.y);
        __nv_bfloat162 p1 = __floats2bfloat162_rn(v.z, v.w);
        uint2 pk;
        pk.x = *reinterpret_cast<uint32_t*>(&p0);
        pk.y = *reinterpret_cast<uint32_t*>(&p1);
        *reinterpret_cast<uint2*>(dst + idx) = pk;
    }
    #pragma unroll
    for (int o = 16; o > 0; o >>= 1) s += __shfl_xor_sync(0xffffffffu, s, o);
    if (lane == 0) *nrm = s;
}

// ============================ GEMM kernel ============================
// CTA 128x128 output tile, 256 threads: 8 warps in 2(M) x 4(N), warp tile
// 64x32 (64 fp32 acc regs/thread). 97KB smem/CTA -> 2 CTAs/SM -> 16 warps/SM
// = 4 warps/SMSP: when one CTA sits at its chunk barrier, the other CTA still
// has 2 runnable warps per SMSP to keep the HMMA pipe full (TLP replaces the
// manual fragment double-buffering, which no longer fits the register file).
// SMEM tiles K-major, 128B rows (TK=64 bf16), XOR-swizzled: granule column
// c (16B units, 0..7) stored at column c ^ (row & 7).
// 3-stage cp.async pipeline: wait_group 1 guarantees chunk kc resident at
// compute of kc; chunk kc+2's loads are issued interleaved with the k16 steps.

// prologue-only: load one full stage at once (256 threads)
__device__ __forceinline__ void load_stage(uint32_t abuf, uint32_t bbuf,
                                           const __nv_bfloat16* Ag,
                                           const __nv_bfloat16* Bg,
                                           int kc, int tid) {
    #pragma unroll
    for (int i = 0; i < 4; i++) {            // A: 1024 granules / 256 threads
        int g = i * 256 + tid;
        int row = g >> 3, c = g & 7;
        uint32_t sm = abuf + row * 128 + ((c ^ (row & 7)) << 4);
        const void* gp = Ag + (size_t)row * DDIM + kc * TK + c * 8;
        CP_ASYNC16(sm, gp);
    }
    #pragma unroll
    for (int i = 0; i < 4; i++) {            // B: 1024 granules
        int g = i * 256 + tid;
        int row = g >> 3, c = g & 7;
        uint32_t sm = bbuf + row * 128 + ((c ^ (row & 7)) << 4);
        const void* gp = Bg + (size_t)row * DDIM + kc * TK + c * 8;
        CP_ASYNC16(sm, gp);
    }
}

__global__ __launch_bounds__(256, 2) void gemm_kernel(float* __restrict__ out) {
    extern __shared__ char smem_raw[];
    uint32_t sb0 = smem_u32(smem_raw);
    uint32_t sb = (sb0 + 1023u) & ~1023u;    // 1024-align tile base

    int tid = threadIdx.x;
    int lane = tid & 31;
    int wid = tid >> 5;
    int warp_m = wid & 1;                    // 0..1  (64-row slab)
    int warp_n = wid >> 1;                   // 0..3  (32-col slab)

    // ldmatrix per-lane row/k-half selection
    int a_row = (lane & 7) + ((lane >> 3) & 1) * 8;   // mats: r0-7/k0, r8-15/k0, r0-7/k8, r8-15/k8
    int a_kb  = (lane >> 4) & 1;
    int b_row = (lane & 7) + ((lane >> 4) & 1) * 8;   // mats: n0-7/k0, n0-7/k8, n8-15/k0, n8-15/k8
    int b_kb  = (lane >> 3) & 1;
    int arx = a_row & 7;
    int brx = b_row & 7;

    float acc[4][4][4];                      // [m16 tile][n8 tile][frag]
    #pragma unroll
    for (int mi = 0; mi < 4; mi++)
        #pragma unroll
        for (int ni = 0; ni < 4; ni++)
            #pragma unroll
            for (int j = 0; j < 4; j++) acc[mi][ni][j] = 0.0f;

    const __nv_bfloat16* Ag = g_feat_bf16 + (size_t)blockIdx.y * TM * DDIM;
    const __nv_bfloat16* Bg = g_cent_bf16 + (size_t)blockIdx.x * TN * DDIM;

    // prologue: stages 0,1
    #pragma unroll
    for (int s = 0; s < NSTAGE - 1; s++) {
        uint32_t ab = sb + s * STAGE_BYTES;
        load_stage(ab, ab + A_STAGE_BYTES, Ag, Bg, s, tid);
        CP_ASYNC_COMMIT();
    }

    // per-thread granule coords for interleaved next-stage loads:
    // per k16 step each thread issues 1 A granule + 1 B granule (32-row group)
    int l_row = tid >> 3;                    // 0..31
    int l_c   = tid & 7;
    uint32_t l_sw = ((uint32_t)(l_c ^ (l_row & 7))) << 4;

    for (int kc = 0; kc < KCHUNKS; kc++) {
        CP_ASYNC_WAIT1();         // chunk kc complete (kc+1's group may be in flight)
        __syncthreads();          // stage kc resident CTA-wide; stage (kc+2)%3 free

        uint32_t cbuf = sb + (kc % NSTAGE) * STAGE_BYTES;
        int lkc = kc + 2;
        bool do_load = (lkc < KCHUNKS);
        uint32_t lbuf = sb + (lkc % NSTAGE) * STAGE_BYTES;

        uint32_t a_base = cbuf + (warp_m * 64 + a_row) * 128;
        uint32_t b_base = cbuf + A_STAGE_BYTES + (warp_n * 32 + b_row) * 128;

        #pragma unroll
        for (int k16 = 0; k16 < K16S; k16++) {
            // fragments for this k16 step (single-buffered; TLP hides latency)
            uint32_t af[4][4];
            #pragma unroll
            for (int mi = 0; mi < 4; mi++) {
                uint32_t ad = a_base + mi * (16 * 128) + (((k16 * 2 + a_kb) ^ arx) << 4);
                LDSM_X4(af[mi], ad);
            }
            uint32_t bf[2][4];     // 2 x4-LDSM cover 32 cols
            #pragma unroll
            for (int ng = 0; ng < 2; ng++) {
                uint32_t bd = b_base + ng * (16 * 128) + (((k16 * 2 + b_kb) ^ brx) << 4);
                LDSM_X4(bf[ng], bd);
            }
            // interleaved slice of chunk kc+2 loads: 1 A + 1 B granule
            if (do_load) {
                int row = k16 * 32 + l_row;
                uint32_t sma = lbuf + row * 128 + l_sw;
                CP_ASYNC16(sma, Ag + (size_t)row * DDIM + lkc * TK + l_c * 8);
                uint32_t smb = lbuf + A_STAGE_BYTES + row * 128 + l_sw;
                CP_ASYNC16(smb, Bg + (size_t)row * DDIM + lkc * TK + l_c * 8);
            }
            #pragma unroll
            for (int mi = 0; mi < 4; mi++)
                #pragma unroll
                for (int ni = 0; ni < 4; ni++)
                    MMA_BF16(acc[mi][ni], af[mi], bf[ni >> 1][(ni & 1) * 2],
                             bf[ni >> 1][(ni & 1) * 2 + 1]);
        }
        CP_ASYNC_COMMIT();        // one group per chunk (empty in tail)
    }

    // ---------------- epilogue: dist = x2 + c2 - 2*acc ----------------
    int qid = lane >> 2;          // 0..7 row-in-8
    int tig = lane & 3;           // 0..3 col pair
    int row_base = blockIdx.y * TM + warp_m * 64;
    int col_base = blockIdx.x * TN + warp_n * 32;

    #pragma unroll
    for (int mi = 0; mi < 4; mi++) {
        int r0 = row_base + mi * 16 + qid;
        float x2a = __ldg(&g_x2[r0]);
        float x2b = __ldg(&g_x2[r0 + 8]);
        float* o0 = out + (size_t)r0 * C_ROWS;
        float* o1 = out + (size_t)(r0 + 8) * C_ROWS;
        #pragma unroll
        for (int ni = 0; ni < 4; ni++) {
            int c = col_base + ni * 8 + tig * 2;
            float c2x = __ldg(&g_c2[c]);
            float c2y = __ldg(&g_c2[c + 1]);
            float2 v0, v1;
            v0.x = fmaf(-2.0f, acc[mi][ni][0], x2a + c2x);
            v0.y = fmaf(-2.0f, acc[mi][ni][1], x2a + c2y);
            v1.x = fmaf(-2.0f, acc[mi][ni][2], x2b + c2x);
            v1.y = fmaf(-2.0f, acc[mi][ni][3], x2b + c2y);
            *reinterpret_cast<float2*>(o0 + c) = v0;
            *reinterpret_cast<float2*>(o1 + c) = v1;
        }
    }
}

// ============================ launch ============================
extern "C" void kernel_launch(void* const* d_in, const int* in_sizes, int n_in,
                              void* d_out, int out_size) {
    const float* feat = (const float*)d_in[0];
    const float* cent = (const float*)d_in[1];
    float* out = (float*)d_out;

    int nwarps = B_ROWS + C_ROWS;
    prep_kernel<<<(nwarps + 7) / 8, 256>>>(feat, cent);

    cudaFuncSetAttribute(gemm_kernel, cudaFuncAttributeMaxDynamicSharedMemorySize, SMEM_DYN);
    dim3 grid(C_ROWS / TN, B_ROWS / TM);   // (32, 128): x fastest -> wave shares B panel in L2
    gemm_kernel<<<grid, 256, SMEM_DYN>>>(out);
}

// round 13
// speedup vs baseline: 1.0545x; 1.0545x over previous
#include <cuda_runtime.h>
#include <cuda_bf16.h>
#include <cstdint>

#define B_ROWS 16384
#define C_ROWS 4096
#define DDIM   1024

// GEMM tiling
#define TM 128            // CTA M
#define TN 128            // CTA N
#define TK 64             // K chunk (per pipeline stage)
#define NSTAGE 3
#define KCHUNKS (DDIM / TK)        // 16
#define K16S (TK / 16)             // 4 mma k-steps per chunk

#define A_STAGE_BYTES (TM * TK * 2)            // 16384
#define B_STAGE_BYTES (TN * TK * 2)            // 16384
#define STAGE_BYTES (A_STAGE_BYTES + B_STAGE_BYTES)   // 32768
#define SMEM_DYN (1024 + NSTAGE * STAGE_BYTES)        // 99328  -> 2 CTAs/SM

// ---- device scratch (allocation-free rule: __device__ globals) ----
__device__ __align__(16) __nv_bfloat16 g_feat_bf16[B_ROWS * DDIM];   // 32 MB
__device__ __align__(16) __nv_bfloat16 g_cent_bf16[C_ROWS * DDIM];   // 8 MB
__device__ float g_x2[B_ROWS];
__device__ float g_c2[C_ROWS];

// ============================ PTX helpers (baseline PTX only) ============================
__device__ __forceinline__ uint32_t smem_u32(const void* p) {
    return (uint32_t)__cvta_generic_to_shared(p);
}

#define CP_ASYNC16(smem_addr, gptr) \
    asm volatile("cp.async.cg.shared.global [%0], [%1], 16;" \
                 :: "r"((uint32_t)(smem_addr)), "l"(gptr) : "memory")

#define CP_ASYNC_COMMIT() asm volatile("cp.async.commit_group;" ::: "memory")
#define CP_ASYNC_WAIT1()  asm volatile("cp.async.wait_group 1;" ::: "memory")
#define CP_ASYNC_WAIT0()  asm volatile("cp.async.wait_group 0;" ::: "memory")

#define LDSM_X4(r, addr) \
    asm volatile("ldmatrix.sync.aligned.m8n8.x4.shared.b16 {%0,%1,%2,%3}, [%4];" \
                 : "=r"((r)[0]), "=r"((r)[1]), "=r"((r)[2]), "=r"((r)[3]) \
                 : "r"((uint32_t)(addr)))

#define MMA_BF16(d, a, b0, b1) \
    asm volatile("mma.sync.aligned.m16n8k16.row.col.f32.bf16.bf16.f32 " \
                 "{%0,%1,%2,%3}, {%4,%5,%6,%7}, {%8,%9}, {%0,%1,%2,%3};" \
                 : "+f"((d)[0]), "+f"((d)[1]), "+f"((d)[2]), "+f"((d)[3]) \
                 : "r"((a)[0]), "r"((a)[1]), "r"((a)[2]), "r"((a)[3]), \
                   "r"(b0), "r"(b1))

// ============================ prep kernel ============================
// One warp per row: fp32 -> bf16 + squared row norm. 20480 warps.
__global__ void prep_kernel(const float* __restrict__ feat, const float* __restrict__ cent) {
    int gw = (blockIdx.x * blockDim.x + threadIdx.x) >> 5;
    int lane = threadIdx.x & 31;
    if (gw >= B_ROWS + C_ROWS) return;

    const float* src;
    __nv_bfloat16* dst;
    float* nrm;
    if (gw < B_ROWS) {
        src = feat + (size_t)gw * DDIM;
        dst = g_feat_bf16 + (size_t)gw * DDIM;
        nrm = g_x2 + gw;
    } else {
        int r = gw - B_ROWS;
        src = cent + (size_t)r * DDIM;
        dst = g_cent_bf16 + (size_t)r * DDIM;
        nrm = g_c2 + r;
    }

    float s = 0.0f;
    #pragma unroll
    for (int i = 0; i < DDIM / 128; i++) {
        int idx = i * 128 + lane * 4;
        float4 v = *reinterpret_cast<const float4*>(src + idx);
        s = fmaf(v.x, v.x, s); s = fmaf(v.y, v.y, s);
        s = fmaf(v.z, v.z, s); s = fmaf(v.w, v.w, s);
        __nv_bfloat162 p0 = __floats2bfloat162_rn(v.x, v.y);
        __nv_bfloat162 p1 = __floats2bfloat162_rn(v.z, v.w);
        uint2 pk;
        pk.x = *reinterpret_cast<uint32_t*>(&p0);
        pk.y = *reinterpret_cast<uint32_t*>(&p1);
        *reinterpret_cast<uint2*>(dst + idx) = pk;
    }
    #pragma unroll
    for (int o = 16; o > 0; o >>= 1) s += __shfl_xor_sync(0xffffffffu, s, o);
    if (lane == 0) *nrm = s;
}

// ============================ GEMM kernel ============================
// CTA 128x128 output tile, 4 warps in 2(M) x 2(N), warp tile 64x64.
// 128 threads/CTA, 97KB smem/CTA -> 2 CTAs/SM.
// SMEM tiles K-major, 128B rows (TK=64 bf16), XOR-swizzled.
// 3-stage cp.async pipeline with MID-CHUNK synchronization: the per-chunk
// wait_group 0 + __syncthreads() sits between k16=2 and k16=3, at which point
// frags for k16=3 are already in registers, and k16=3 prefetches chunk kc+1's
// first fragments from the now-guaranteed-resident next stage. Result: no
// LDSM (and no MMA-starving bootstrap) ever follows a barrier.
// Hazards: writes to buffer (kc+2)%3 start at k16=0 of chunk kc; last reads
// of that buffer (as stage kc-1) end before chunk kc-1's mid-chunk barrier
// (WAR safe). Reads of stage kc+1 happen only after wait0+barrier (RAW safe).

// prologue-only: load one full stage at once (128 threads)
__device__ __forceinline__ void load_stage(uint32_t abuf, uint32_t bbuf,
                                           const __nv_bfloat16* Ag,
                                           const __nv_bfloat16* Bg,
                                           int kc, int tid) {
    #pragma unroll
    for (int i = 0; i < 8; i++) {            // A: 1024 granules / 128 threads
        int g = i * 128 + tid;
        int row = g >> 3, c = g & 7;
        uint32_t sm = abuf + row * 128 + ((c ^ (row & 7)) << 4);
        const void* gp = Ag + (size_t)row * DDIM + kc * TK + c * 8;
        CP_ASYNC16(sm, gp);
    }
    #pragma unroll
    for (int i = 0; i < 8; i++) {            // B: 1024 granules
        int g = i * 128 + tid;
        int row = g >> 3, c = g & 7;
        uint32_t sm = bbuf + row * 128 + ((c ^ (row & 7)) << 4);
        const void* gp = Bg + (size_t)row * DDIM + kc * TK + c * 8;
        CP_ASYNC16(sm, gp);
    }
}

// load af[buf]/bf[buf] fragments for one k16 step from a given stage
#define LOAD_FRAGS(buf, stage_addr, k16_) do {                                   \
    uint32_t a_base_ = (stage_addr) + (warp_m * 64 + a_row) * 128;               \
    uint32_t b_base_ = (stage_addr) + A_STAGE_BYTES + (warp_n * 64 + b_row) * 128; \
    _Pragma("unroll")                                                            \
    for (int mi_ = 0; mi_ < 4; mi_++) {                                          \
        uint32_t ad_ = a_base_ + mi_ * (16 * 128) + ((((k16_) * 2 + a_kb) ^ arx) << 4); \
        LDSM_X4(af[buf][mi_], ad_);                                              \
    }                                                                            \
    _Pragma("unroll")                                                            \
    for (int ng_ = 0; ng_ < 4; ng_++) {                                          \
        uint32_t bd_ = b_base_ + ng_ * (16 * 128) + ((((k16_) * 2 + b_kb) ^ brx) << 4); \
        LDSM_X4(bf[buf][ng_], bd_);                                              \
    }                                                                            \
} while (0)

__global__ __launch_bounds__(128, 2) void gemm_kernel(float* __restrict__ out) {
    extern __shared__ char smem_raw[];
    uint32_t sb0 = smem_u32(smem_raw);
    uint32_t sb = (sb0 + 1023u) & ~1023u;    // 1024-align tile base

    int tid = threadIdx.x;
    int lane = tid & 31;
    int wid = tid >> 5;
    int warp_m = wid & 1;                    // 0..1
    int warp_n = wid >> 1;                   // 0..1

    // ldmatrix per-lane row/k-half selection
    int a_row = (lane & 7) + ((lane >> 3) & 1) * 8;   // mats: r0-7/k0, r8-15/k0, r0-7/k8, r8-15/k8
    int a_kb  = (lane >> 4) & 1;
    int b_row = (lane & 7) + ((lane >> 4) & 1) * 8;   // mats: n0-7/k0, n0-7/k8, n8-15/k0, n8-15/k8
    int b_kb  = (lane >> 3) & 1;
    int arx = a_row & 7;
    int brx = b_row & 7;

    float acc[4][8][4];
    #pragma unroll
    for (int mi = 0; mi < 4; mi++)
        #pragma unroll
        for (int ni = 0; ni < 8; ni++)
            #pragma unroll
            for (int j = 0; j < 4; j++) acc[mi][ni][j] = 0.0f;

    uint32_t af[2][4][4];
    uint32_t bf[2][4][4];   // [buf][ng]: {b0,b1} of n-tile 2ng, {b0,b1} of 2ng+1

    const __nv_bfloat16* Ag = g_feat_bf16 + (size_t)blockIdx.y * TM * DDIM;
    const __nv_bfloat16* Bg = g_cent_bf16 + (size_t)blockIdx.x * TN * DDIM;

    // prologue: stages 0,1
    #pragma unroll
    for (int s = 0; s < NSTAGE - 1; s++) {
        uint32_t ab = sb + s * STAGE_BYTES;
        load_stage(ab, ab + A_STAGE_BYTES, Ag, Bg, s, tid);
        CP_ASYNC_COMMIT();
    }
    CP_ASYNC_WAIT1();         // stage 0 complete (stage 1's group may be in flight)
    __syncthreads();          // stage 0 visible CTA-wide

    // per-thread granule coordinates for the interleaved next-stage loads:
    // per k16 step this thread issues 2 A granules + 2 B granules.
    int l_row = tid >> 3;                    // 0..15
    int l_c   = tid & 7;
    uint32_t l_sw = ((uint32_t)(l_c ^ (l_row & 7))) << 4;   // row%8 == l_row%8 (16-row groups)

    int pb = 0;
    LOAD_FRAGS(0, sb, 0);     // bootstrap frags(chunk0, k16=0) — only exposed LDSM

    for (int kc = 0; kc < KCHUNKS; kc++) {
        uint32_t cbuf = sb + (kc % NSTAGE) * STAGE_BYTES;
        uint32_t nbuf = sb + ((kc + 1) % NSTAGE) * STAGE_BYTES;
        int lkc = kc + 2;
        bool do_load = (lkc < KCHUNKS);
        uint32_t lbuf = sb + (lkc % NSTAGE) * STAGE_BYTES;

        #pragma unroll
        for (int k16 = 0; k16 < K16S; k16++) {
            int cur = pb, nxt = pb ^ 1;
            // intra-chunk fragment prefetch (k16 0..2)
            if (k16 < K16S - 1) LOAD_FRAGS(nxt, cbuf, k16 + 1);
            // interleaved slice of chunk kc+2 loads: 2 A + 2 B granules
            if (do_load) {
                #pragma unroll
                for (int j = 0; j < 2; j++) {
                    int row = (k16 * 2 + j) * 16 + l_row;
                    uint32_t sma = lbuf + row * 128 + l_sw;
                    CP_ASYNC16(sma, Ag + (size_t)row * DDIM + lkc * TK + l_c * 8);
                    uint32_t smb = lbuf + A_STAGE_BYTES + row * 128 + l_sw;
                    CP_ASYNC16(smb, Bg + (size_t)row * DDIM + lkc * TK + l_c * 8);
                }
            }
            // mid-chunk sync: frags(kc,3) already in regs; next MMAs ready to go
            if (k16 == K16S - 2) {
                CP_ASYNC_WAIT0();      // group(kc+1) — committed a full chunk ago
                __syncthreads();       // stage kc+1 visible; buffer (kc+2)%3 free
            }
            // cross-chunk fragment prefetch from the now-resident next stage
            if (k16 == K16S - 1 && kc + 1 < KCHUNKS) LOAD_FRAGS(nxt, nbuf, 0);

            #pragma unroll
            for (int mi = 0; mi < 4; mi++)
                #pragma unroll
                for (int ni = 0; ni < 8; ni++)
                    MMA_BF16(acc[mi][ni], af[cur][mi], bf[cur][ni >> 1][(ni & 1) * 2],
                             bf[cur][ni >> 1][(ni & 1) * 2 + 1]);
            pb ^= 1;
        }
        CP_ASYNC_COMMIT();        // one group per chunk (empty in tail)
    }

    // ---------------- epilogue: dist = x2 + c2 - 2*acc ----------------
    int qid = lane >> 2;          // 0..7 row-in-8
    int tig = lane & 3;           // 0..3 col pair
    int row_base = blockIdx.y * TM + warp_m * 64;
    int col_base = blockIdx.x * TN + warp_n * 64;

    #pragma unroll
    for (int mi = 0; mi < 4; mi++) {
        int r0 = row_base + mi * 16 + qid;
        float x2a = __ldg(&g_x2[r0]);
        float x2b = __ldg(&g_x2[r0 + 8]);
        float* o0 = out + (size_t)r0 * C_ROWS;
        float* o1 = out + (size_t)(r0 + 8) * C_ROWS;
        #pragma unroll
        for (int ni = 0; ni < 8; ni++) {
            int c = col_base + ni * 8 + tig * 2;
            float c2x = __ldg(&g_c2[c]);
            float c2y = __ldg(&g_c2[c + 1]);
            float2 v0, v1;
            v0.x = fmaf(-2.0f, acc[mi][ni][0], x2a + c2x);
            v0.y = fmaf(-2.0f, acc[mi][ni][1], x2a + c2y);
            v1.x = fmaf(-2.0f, acc[mi][ni][2], x2b + c2x);
            v1.y = fmaf(-2.0f, acc[mi][ni][3], x2b + c2y);
            *reinterpret_cast<float2*>(o0 + c) = v0;
            *reinterpret_cast<float2*>(o1 + c) = v1;
        }
    }
}

// ============================ launch ============================
extern "C" void kernel_launch(void* const* d_in, const int* in_sizes, int n_in,
                              void* d_out, int out_size) {
    const float* feat = (const float*)d_in[0];
    const float* cent = (const float*)d_in[1];
    float* out = (float*)d_out;

    int nwarps = B_ROWS + C_ROWS;
    prep_kernel<<<(nwarps + 7) / 8, 256>>>(feat, cent);

    cudaFuncSetAttribute(gemm_kernel, cudaFuncAttributeMaxDynamicSharedMemorySize, SMEM_DYN);
    dim3 grid(C_ROWS / TN, B_ROWS / TM);   // (32, 128): x fastest -> wave shares B panel in L2
    gemm_kernel<<<grid, 128, SMEM_DYN>>>(out);
}